// round 15
// baseline (speedup 1.0000x reference)
#include <cuda_runtime.h>
#include <cuda_fp16.h>
#include <cstdint>

// v14 = v13 with the K-ring stride bug fixed (2048 uint2 per slot, not 4096).
// B=8, M=3, H=W=96, C=128, NS=4 -> 128 windows, L=576, KV=1728.
//  prep_kv2: gather per window; K -> fp16 (hi,lo) interleaved uint2;
//            V -> fp16 TRANSPOSED [win][tile][ch][kvpair] fp16x2.
//  mv_attn_tc14: QK^T = Qh*Kh + Qh*Kl (fp16 m16n8k16, Q single-plane,
//            term-split accumulators for ILP). PV = fp16 m16n8k16.
//            Fixed-max softmax; l reduced once at end. Depth-3 cp.async
//            ring (prefetch distance 2), one commit group per iteration.
// CTA: 256 thr (8 warps), 64 q rows; warp pair owns 16 rows; sub s=warp&1:
// S on kv half (16 rows), PV on channel half (64). KVT=32.

#define NT 256
#define KVT 32
#define NTILES 54
#define NWIN 128
#define KVLEN 1728

__device__ uint2    g_Khl [(size_t)NWIN * KVLEN * 64];     // (hi,lo) fp16x2 / 2ch
__device__ uint32_t g_Vt16[(size_t)NWIN * NTILES * 2048];  // [win][tile][ch][pair]

// smem word offsets
#define QH_W    0          // u32 [64][64]              4096
#define KHL_W   4096       // uint2[3][2048]            12288 words
#define VT_W    16384      // u32 [3][128][20]          7680
#define PB_W    24064      // u32 [64][20]              1280
#define SMB_W   25344      // f32 [2][64]               128
#define REGK_W  25472      // char[1728]                432 words
#define SMEM_BYTES (25904 * 4)   // 103616

__device__ __forceinline__ uint32_t hbits(__half2 h) {
    return *reinterpret_cast<uint32_t*>(&h);
}
__device__ __forceinline__ void cp16(uint32_t dst, const void* src) {
    asm volatile("cp.async.cg.shared.global [%0], [%1], 16;" :: "r"(dst), "l"(src));
}
__device__ __forceinline__ void cp_commit() {
    asm volatile("cp.async.commit_group;" ::: "memory");
}
__device__ __forceinline__ void cp_wait1() {
    asm volatile("cp.async.wait_group 1;" ::: "memory");
}
__device__ __forceinline__ void mma16h(float c[4],
    uint32_t a0, uint32_t a1, uint32_t a2, uint32_t a3, uint32_t b0, uint32_t b1) {
    asm volatile("mma.sync.aligned.m16n8k16.row.col.f32.f16.f16.f32 "
        "{%0,%1,%2,%3},{%4,%5,%6,%7},{%8,%9},{%0,%1,%2,%3};"
        : "+f"(c[0]), "+f"(c[1]), "+f"(c[2]), "+f"(c[3])
        : "r"(a0), "r"(a1), "r"(a2), "r"(a3), "r"(b0), "r"(b1));
}
__device__ __forceinline__ int reg1(int x) { return (x < 72) ? 0 : ((x < 84) ? 1 : 2); }

// ============ prep: gather+convert K, gather+transpose V ============
extern "C" __global__ void __launch_bounds__(256)
prep_kv2(const float* __restrict__ kg, const float* __restrict__ vg)
{
    __shared__ uint16_t sv[128 * 64];
    const int tid = threadIdx.x, blk = blockIdx.x;
    const int win = blk / 27, kb = blk - win * 27;
    const int kvbase = kb * 64;
    const int b = win >> 4, sh = (win >> 2) & 3, sw = win & 3;

    #pragma unroll
    for (int e = 0; e < 8; ++e) {
        int idx = tid + e * 256;
        int kvl = idx >> 5, c4 = (idx & 31) << 2;
        int kv = kvbase + kvl;
        int l = kv / 3, mm = kv - 3 * l;
        int i = l / 24, j = l - 24 * i;
        int grow = (sh * 24 + i + 12) % 96;
        int gcol = (sw * 24 + j + 12) % 96;
        size_t src = (((size_t)((b * 3 + mm) * 9216 + grow * 96 + gcol)) << 7) + c4;

        float4 kf = *(const float4*)(kg + src);
        __half2 h0 = __floats2half2_rn(kf.x, kf.y);
        __half2 h1 = __floats2half2_rn(kf.z, kf.w);
        float2 r0 = __half22float2(h0), r1 = __half22float2(h1);
        __half2 e0 = __floats2half2_rn(kf.x - r0.x, kf.y - r0.y);
        __half2 e1 = __floats2half2_rn(kf.z - r1.x, kf.w - r1.y);
        size_t dst = (size_t)win * (KVLEN * 64) + (size_t)kv * 64 + (c4 >> 1);
        *(uint4*)(g_Khl + dst) = make_uint4(hbits(h0), hbits(e0), hbits(h1), hbits(e1));

        float4 vf = *(const float4*)(vg + src);
        float vv[4] = {vf.x, vf.y, vf.z, vf.w};
        #pragma unroll
        for (int k2 = 0; k2 < 4; ++k2) {
            int ch = c4 + k2;
            __half vh = __float2half_rn(vv[k2]);
            sv[ch * 64 + (kvl ^ ((ch & 31) << 1))] = *reinterpret_cast<uint16_t*>(&vh);
        }
    }
    __syncthreads();

    const uint32_t* svw = (const uint32_t*)sv;
    #pragma unroll
    for (int it = 0; it < 16; ++it) {
        int idx = tid + it * 256;
        int ch = idx >> 5, kp = idx & 31;
        uint32_t w = svw[ch * 32 + (kp ^ (ch & 31))];
        int tile = kb * 2 + (kp >> 4);
        int pr   = kp & 15;
        g_Vt16[(size_t)(win * NTILES + tile) * 2048 + ch * 16 + pr] = w;
    }
}

// ============ main attention kernel ============
extern "C" __global__ void __launch_bounds__(NT, 2)
mv_attn_tc14(const float* __restrict__ qg, float* __restrict__ outg)
{
    extern __shared__ float smem[];
    uint32_t* QhS = (uint32_t*)smem + QH_W;
    uint32_t* PbU = (uint32_t*)smem + PB_W;
    float*    SMB = smem + SMB_W;
    char*     regK = (char*)(smem + REGK_W);
    const uint32_t smem_u32 = (uint32_t)__cvta_generic_to_shared(smem);
    const uint32_t khl_b = smem_u32 + KHL_W * 4;
    const uint32_t vt_b  = smem_u32 + VT_W * 4;

    const int tid  = threadIdx.x;
    const int warp = tid >> 5;
    const int lane = tid & 31;
    const int gr   = lane >> 2;
    const int tig  = lane & 3;
    const int pair = warp >> 1;
    const int s    = warp & 1;
    const int woff = pair << 4;

    const int win = blockIdx.y;
    const int b   = win >> 4;
    const int sh  = (win >> 2) & 3;
    const int sw  = win & 3;
    const int q0  = blockIdx.x << 6;

    const float scale = 0.08838834764831845f;
    const size_t wb64 = (size_t)win * (KVLEN * 64);

    const int kr = tid >> 3;
    const int kp = (tid & 7) << 3;

    // ---- region LUT (tile() quirk: mask column = kv % 576) ----
    for (int idx = tid; idx < KVLEN; idx += NT) {
        int kcol = idx % 576;
        int i = kcol / 24, j = kcol - 24 * i;
        regK[idx] = (char)(reg1(sh * 24 + i) * 3 + reg1(sw * 24 + j));
    }

    // prefetch tile tt into ring slot tt%3 (K slot = 2048 uint2, V slot = 2560 u32)
    #define PREFETCH_TILE(tt) do {                                            \
        const int rb_ = (tt) % 3;                                             \
        const uint2* ksrc_ = g_Khl + wb64 + (size_t)((tt) * KVT + kr) * 64;   \
        _Pragma("unroll")                                                     \
        for (int u = 0; u < 4; ++u) {                                         \
            int p_  = kp + (u << 1);                                          \
            int pk_ = p_ ^ ((kr & 7) << 2);                                   \
            cp16(khl_b + (rb_ * 2048 + kr * 64 + pk_) * 8, ksrc_ + p_);       \
        }                                                                     \
        const uint32_t* vsrc_ = g_Vt16 + (size_t)(win * NTILES + (tt)) * 2048;\
        _Pragma("unroll")                                                     \
        for (int u = 0; u < 2; ++u) {                                         \
            int c_ = tid + u * 256;                                           \
            int ch_ = c_ >> 2, g_ = c_ & 3;                                   \
            cp16(vt_b + (rb_ * 2560 + ch_ * 20 + g_ * 4) * 4,                 \
                 vsrc_ + ch_ * 16 + g_ * 4);                                  \
        }                                                                     \
    } while (0)

    PREFETCH_TILE(0); cp_commit();
    PREFETCH_TILE(1); cp_commit();

    // ---- Q: gather + scale + single-plane fp16 into smem ----
    #pragma unroll
    for (int it = 0; it < 8; ++it) {
        int idx = tid + it * NT;
        int r   = idx >> 5;
        int c4  = (idx & 31) << 2;
        int ql  = q0 + r;
        int i = ql / 24, j = ql - 24 * i;
        int grow = (sh * 24 + i + 12) % 96;
        int gcol = (sw * 24 + j + 12) % 96;
        float4 f = *(const float4*)(qg + ((size_t)(b * 9216 + grow * 96 + gcol) << 7) + c4);
        __half2 h0 = __floats2half2_rn(f.x * scale, f.y * scale);
        __half2 h1 = __floats2half2_rn(f.z * scale, f.w * scale);
        int ps = (c4 >> 1) ^ ((r & 7) << 2);
        *(uint2*)&QhS[r * 64 + ps] = make_uint2(hbits(h0), hbits(h1));
    }

    int rq0, rq1;
    {
        int ql = q0 + woff + gr;
        int i = ql / 24, j = ql - 24 * i;
        rq0 = reg1(sh * 24 + i) * 3 + reg1(sw * 24 + j);
        ql += 8; i = ql / 24; j = ql - 24 * i;
        rq1 = reg1(sh * 24 + i) * 3 + reg1(sw * 24 + j);
    }

    float O[8][4];
    #pragma unroll
    for (int nt = 0; nt < 8; ++nt)
        #pragma unroll
        for (int v = 0; v < 4; ++v) O[nt][v] = 0.0f;
    float l0s = 0.0f, l1s = 0.0f;

    const int kvsub = s << 4;
    const int pbase = s << 3;
    const int cbase = s << 6;
    const int barid = 1 + pair;

    for (int t = 0; t < NTILES; ++t) {
        const int kv0 = t * KVT;
        const int buf = t % 3;
        cp_wait1();        // group(t) complete; group(t+1) may still fly
        __syncthreads();   // compute on slot buf (tile t-3) finished

        if (t + 2 < NTILES) PREFETCH_TILE(t + 2);
        cp_commit();       // exactly one group per iteration (may be empty)

        const uint2*    KhlS = (const uint2*)(smem + KHL_W) + buf * 2048;
        const uint32_t* Vt   = (const uint32_t*)smem + VT_W + buf * 2560;

        // ---- S: Sh = Qh·Kh, Sl = Qh·Kl (4 independent mma chains) ----
        float Sh[2][4], Sl[2][4];
        #pragma unroll
        for (int nt = 0; nt < 2; ++nt)
            #pragma unroll
            for (int v = 0; v < 4; ++v) { Sh[nt][v] = 0.0f; Sl[nt][v] = 0.0f; }

        const int sA = gr << 2;
        #pragma unroll
        for (int st = 0; st < 8; ++st) {
            int pp  = (st << 3) + tig;
            int pA0 = pp ^ sA;
            int pA1 = (pp + 4) ^ sA;
            uint32_t a0 = QhS[(woff + gr) * 64 + pA0];
            uint32_t a1 = QhS[(woff + gr + 8) * 64 + pA0];
            uint32_t a2 = QhS[(woff + gr) * 64 + pA1];
            uint32_t a3 = QhS[(woff + gr + 8) * 64 + pA1];
            #pragma unroll
            for (int nt = 0; nt < 2; ++nt) {
                int kvr = kvsub + (nt << 3) + gr;
                uint2 b0 = KhlS[kvr * 64 + pA0];
                uint2 b1 = KhlS[kvr * 64 + pA1];
                mma16h(Sh[nt], a0, a1, a2, a3, b0.x, b1.x);
                mma16h(Sl[nt], a0, a1, a2, a3, b0.y, b1.y);
            }
        }

        // ---- mask + exp (fixed-max) + stage P (fp16x2) + local l ----
        #pragma unroll
        for (int nt = 0; nt < 2; ++nt) {
            int kvb = kv0 + kvsub + (nt << 3) + (tig << 1);
            int rk0 = regK[kvb], rk1 = regK[kvb + 1];
            float s0 = Sh[nt][0] + Sl[nt][0];
            float s1 = Sh[nt][1] + Sl[nt][1];
            float s2 = Sh[nt][2] + Sl[nt][2];
            float s3 = Sh[nt][3] + Sl[nt][3];
            float p0 = __expf(rq0 != rk0 ? s0 - 100.0f : s0);
            float p1 = __expf(rq0 != rk1 ? s1 - 100.0f : s1);
            float p2 = __expf(rq1 != rk0 ? s2 - 100.0f : s2);
            float p3 = __expf(rq1 != rk1 ? s3 - 100.0f : s3);
            l0s += p0 + p1;
            l1s += p2 + p3;
            int pc = pbase + (nt << 2) + tig;
            PbU[(woff + gr) * 20 + pc]     = hbits(__floats2half2_rn(p0, p1));
            PbU[(woff + gr + 8) * 20 + pc] = hbits(__floats2half2_rn(p2, p3));
        }
        asm volatile("bar.sync %0, 64;" :: "r"(barid) : "memory");   // pair-local

        // ---- O += P @ V (fp16) on this warp's 64 channels ----
        const uint32_t* Pw = PbU + woff * 20;
        #pragma unroll
        for (int st = 0; st < 2; ++st) {
            int pb = (st << 3) + tig;
            uint32_t a0 = Pw[gr * 20 + pb];
            uint32_t a1 = Pw[(gr + 8) * 20 + pb];
            uint32_t a2 = Pw[gr * 20 + pb + 4];
            uint32_t a3 = Pw[(gr + 8) * 20 + pb + 4];
            #pragma unroll
            for (int nt = 0; nt < 8; ++nt) {
                int ch = cbase + (nt << 3) + gr;
                uint32_t v0 = Vt[ch * 20 + pb];
                uint32_t v1 = Vt[ch * 20 + pb + 4];
                mma16h(O[nt], a0, a1, a2, a3, v0, v1);
            }
        }
    }

    // ---- l reduction: quad shuffle, then cross-sub via smem ----
    l0s += __shfl_xor_sync(0xffffffffu, l0s, 1);
    l0s += __shfl_xor_sync(0xffffffffu, l0s, 2);
    l1s += __shfl_xor_sync(0xffffffffu, l1s, 1);
    l1s += __shfl_xor_sync(0xffffffffu, l1s, 2);
    __syncthreads();
    if (tig == 0) {
        SMB[(s << 6) + woff + gr]     = l0s;
        SMB[(s << 6) + woff + gr + 8] = l1s;
    }
    __syncthreads();
    float lt0 = SMB[woff + gr]     + SMB[64 + woff + gr];
    float lt1 = SMB[woff + gr + 8] + SMB[64 + woff + gr + 8];

    // ---- epilogue: normalize + scatter ----
    float inv0 = 1.0f / lt0, inv1 = 1.0f / lt1;
    int ql0 = q0 + woff + gr;
    int i0 = ql0 / 24, j0 = ql0 - 24 * i0;
    int gr0 = (sh * 24 + i0 + 12) % 96, gc0 = (sw * 24 + j0 + 12) % 96;
    int ql1 = ql0 + 8;
    int i1 = ql1 / 24, j1 = ql1 - 24 * i1;
    int gr1 = (sh * 24 + i1 + 12) % 96, gc1 = (sw * 24 + j1 + 12) % 96;
    float* d0 = outg + ((size_t)(b * 9216 + gr0 * 96 + gc0) << 7) + cbase;
    float* d1 = outg + ((size_t)(b * 9216 + gr1 * 96 + gc1) << 7) + cbase;
    #pragma unroll
    for (int nt = 0; nt < 8; ++nt) {
        int c = (nt << 3) + (tig << 1);
        *(float2*)(d0 + c) = make_float2(O[nt][0] * inv0, O[nt][1] * inv0);
        *(float2*)(d1 + c) = make_float2(O[nt][2] * inv1, O[nt][3] * inv1);
    }
}

extern "C" void kernel_launch(void* const* d_in, const int* in_sizes, int n_in,
                              void* d_out, int out_size)
{
    const float* q = (const float*)d_in[0];
    const float* k = (const float*)d_in[1];
    const float* v = (const float*)d_in[2];
    float* out = (float*)d_out;

    prep_kv2<<<NWIN * 27, 256>>>(k, v);

    cudaFuncSetAttribute(mv_attn_tc14,
                         cudaFuncAttributeMaxDynamicSharedMemorySize, SMEM_BYTES);
    dim3 grid(9, 128, 1);
    mv_attn_tc14<<<grid, NT, SMEM_BYTES>>>(q, out);
}

// round 16
// speedup vs baseline: 1.4246x; 1.4246x over previous
#include <cuda_runtime.h>
#include <cuda_fp16.h>
#include <cstdint>

// v15 = v12 skeleton with SINGLE-PLANE fp16 K (dropped K-lo residual term).
// B=8, M=3, H=W=96, C=128, NS=4 -> 128 windows, L=576, KV=1728.
//  prep_kv2: gather per window; K -> fp16 single plane (fp16x2 per 2ch);
//            V -> fp16 TRANSPOSED [win][tile][ch][kvpair] fp16x2.
//  mv_attn_tc15: QK^T = Qh*Kh (fp16 m16n8k16, fp32 accum; calibrated
//            rel_err ~4.2e-4). PV = fp16 m16n8k16. Fixed-max softmax;
//            l reduced once at end; depth-2 cp.async double buffer;
//            1 CTA sync + 1 pair-local named barrier per tile.
// CTA: 256 thr (8 warps), 64 q rows; warp pair owns 16 rows; sub s=warp&1:
// S on kv half (16 rows), PV on channel half (64). KVT=32.

#define NT 256
#define KVT 32
#define NTILES 54
#define NWIN 128
#define KVLEN 1728

__device__ uint32_t g_Kh  [(size_t)NWIN * KVLEN * 64];     // fp16x2 per 2ch
__device__ uint32_t g_Vt16[(size_t)NWIN * NTILES * 2048];  // [win][tile][ch][pair]

// smem word offsets
#define QH_W    0          // u32 [64][64]              4096
#define KH_W    4096       // u32 [2][32*64]            4096
#define VT_W    8192       // u32 [2][128][20]          5120
#define PB_W    13312      // u32 [64][20]              1280
#define SMB_W   14592      // f32 [2][64]               128
#define REGK_W  14720      // char[1728]                432 words
#define SMEM_BYTES (15152 * 4)   // 60608

__device__ __forceinline__ uint32_t hbits(__half2 h) {
    return *reinterpret_cast<uint32_t*>(&h);
}
__device__ __forceinline__ void cp16(uint32_t dst, const void* src) {
    asm volatile("cp.async.cg.shared.global [%0], [%1], 16;" :: "r"(dst), "l"(src));
}
__device__ __forceinline__ void cp_commit() {
    asm volatile("cp.async.commit_group;" ::: "memory");
}
__device__ __forceinline__ void cp_wait_all() {
    asm volatile("cp.async.wait_group 0;" ::: "memory");
}
__device__ __forceinline__ void mma16h(float c[4],
    uint32_t a0, uint32_t a1, uint32_t a2, uint32_t a3, uint32_t b0, uint32_t b1) {
    asm volatile("mma.sync.aligned.m16n8k16.row.col.f32.f16.f16.f32 "
        "{%0,%1,%2,%3},{%4,%5,%6,%7},{%8,%9},{%0,%1,%2,%3};"
        : "+f"(c[0]), "+f"(c[1]), "+f"(c[2]), "+f"(c[3])
        : "r"(a0), "r"(a1), "r"(a2), "r"(a3), "r"(b0), "r"(b1));
}
__device__ __forceinline__ int reg1(int x) { return (x < 72) ? 0 : ((x < 84) ? 1 : 2); }

// ============ prep: gather+convert K, gather+transpose V ============
// block = (win, 64-kv chunk) -> covers 2 KV tiles. 128*27 blocks.
extern "C" __global__ void __launch_bounds__(256)
prep_kv2(const float* __restrict__ kg, const float* __restrict__ vg)
{
    __shared__ uint16_t sv[128 * 64];   // [ch][kv] fp16, swizzled
    const int tid = threadIdx.x, blk = blockIdx.x;
    const int win = blk / 27, kb = blk - win * 27;
    const int kvbase = kb * 64;
    const int b = win >> 4, sh = (win >> 2) & 3, sw = win & 3;

    #pragma unroll
    for (int e = 0; e < 8; ++e) {
        int idx = tid + e * 256;
        int kvl = idx >> 5, c4 = (idx & 31) << 2;
        int kv = kvbase + kvl;
        int l = kv / 3, mm = kv - 3 * l;
        int i = l / 24, j = l - 24 * i;
        int grow = (sh * 24 + i + 12) % 96;
        int gcol = (sw * 24 + j + 12) % 96;
        size_t src = (((size_t)((b * 3 + mm) * 9216 + grow * 96 + gcol)) << 7) + c4;

        float4 kf = *(const float4*)(kg + src);
        __half2 h0 = __floats2half2_rn(kf.x, kf.y);
        __half2 h1 = __floats2half2_rn(kf.z, kf.w);
        size_t dst = (size_t)win * (KVLEN * 64) + (size_t)kv * 64 + (c4 >> 1);
        *(uint2*)(g_Kh + dst) = make_uint2(hbits(h0), hbits(h1));

        float4 vf = *(const float4*)(vg + src);
        float vv[4] = {vf.x, vf.y, vf.z, vf.w};
        #pragma unroll
        for (int k2 = 0; k2 < 4; ++k2) {
            int ch = c4 + k2;
            __half vh = __float2half_rn(vv[k2]);
            sv[ch * 64 + (kvl ^ ((ch & 31) << 1))] = *reinterpret_cast<uint16_t*>(&vh);
        }
    }
    __syncthreads();

    const uint32_t* svw = (const uint32_t*)sv;   // [ch][32 pairs] swizzled
    #pragma unroll
    for (int it = 0; it < 16; ++it) {
        int idx = tid + it * 256;
        int ch = idx >> 5, kp = idx & 31;
        uint32_t w = svw[ch * 32 + (kp ^ (ch & 31))];
        int tile = kb * 2 + (kp >> 4);
        int pr   = kp & 15;
        g_Vt16[(size_t)(win * NTILES + tile) * 2048 + ch * 16 + pr] = w;
    }
}

// ============ main attention kernel ============
extern "C" __global__ void __launch_bounds__(NT, 2)
mv_attn_tc15(const float* __restrict__ qg, float* __restrict__ outg)
{
    extern __shared__ float smem[];
    uint32_t* QhS = (uint32_t*)smem + QH_W;
    uint32_t* PbU = (uint32_t*)smem + PB_W;
    float*    SMB = smem + SMB_W;
    char*     regK = (char*)(smem + REGK_W);
    const uint32_t smem_u32 = (uint32_t)__cvta_generic_to_shared(smem);
    const uint32_t kh_b = smem_u32 + KH_W * 4;
    const uint32_t vt_b = smem_u32 + VT_W * 4;

    const int tid  = threadIdx.x;
    const int warp = tid >> 5;
    const int lane = tid & 31;
    const int gr   = lane >> 2;
    const int tig  = lane & 3;
    const int pair = warp >> 1;
    const int s    = warp & 1;
    const int woff = pair << 4;

    const int win = blockIdx.y;
    const int b   = win >> 4;
    const int sh  = (win >> 2) & 3;
    const int sw  = win & 3;
    const int q0  = blockIdx.x << 6;

    const float scale = 0.08838834764831845f;   // 1/sqrt(128)
    const size_t wb64 = (size_t)win * (KVLEN * 64);

    // cp.async slots: K 2 uint4/thread, V 2 uint4/thread
    const int kr = tid >> 3;             // 0..31 K row
    const int kp = (tid & 7) << 3;       // u32 position 0,8,..,56

    // ---- region LUT (tile() quirk: mask column = kv % 576) ----
    for (int idx = tid; idx < KVLEN; idx += NT) {
        int kcol = idx % 576;
        int i = kcol / 24, j = kcol - 24 * i;
        regK[idx] = (char)(reg1(sh * 24 + i) * 3 + reg1(sw * 24 + j));
    }

    // ---- prefetch tile 0 into buffer 0 ----
    {
        const uint32_t* ksrc = g_Kh + wb64 + (size_t)kr * 64;
        #pragma unroll
        for (int u = 0; u < 2; ++u) {
            int p  = kp + (u << 2);
            int pk = p ^ ((kr & 7) << 2);
            cp16(kh_b + (kr * 64 + pk) * 4, ksrc + p);
        }
        const uint32_t* vsrc = g_Vt16 + (size_t)(win * NTILES) * 2048;
        #pragma unroll
        for (int u = 0; u < 2; ++u) {
            int c = tid + u * 256;
            int ch = c >> 2, grp = c & 3;
            cp16(vt_b + (ch * 20 + grp * 4) * 4, vsrc + ch * 16 + grp * 4);
        }
        cp_commit();
    }

    // ---- Q: gather + scale + single-plane fp16 into smem ----
    #pragma unroll
    for (int it = 0; it < 8; ++it) {
        int idx = tid + it * NT;
        int r   = idx >> 5;
        int c4  = (idx & 31) << 2;
        int ql  = q0 + r;
        int i = ql / 24, j = ql - 24 * i;
        int grow = (sh * 24 + i + 12) % 96;
        int gcol = (sw * 24 + j + 12) % 96;
        float4 f = *(const float4*)(qg + ((size_t)(b * 9216 + grow * 96 + gcol) << 7) + c4);
        __half2 h0 = __floats2half2_rn(f.x * scale, f.y * scale);
        __half2 h1 = __floats2half2_rn(f.z * scale, f.w * scale);
        int ps = (c4 >> 1) ^ ((r & 7) << 2);
        *(uint2*)&QhS[r * 64 + ps] = make_uint2(hbits(h0), hbits(h1));
    }

    int rq0, rq1;
    {
        int ql = q0 + woff + gr;
        int i = ql / 24, j = ql - 24 * i;
        rq0 = reg1(sh * 24 + i) * 3 + reg1(sw * 24 + j);
        ql += 8; i = ql / 24; j = ql - 24 * i;
        rq1 = reg1(sh * 24 + i) * 3 + reg1(sw * 24 + j);
    }

    float O[8][4];
    #pragma unroll
    for (int nt = 0; nt < 8; ++nt)
        #pragma unroll
        for (int v = 0; v < 4; ++v) O[nt][v] = 0.0f;
    float l0s = 0.0f, l1s = 0.0f;

    const int kvsub = s << 4;      // kv half for S (16 rows)
    const int pbase = s << 3;      // pair base for P staging
    const int cbase = s << 6;      // channel half for PV
    const int barid = 1 + pair;

    for (int t = 0; t < NTILES; ++t) {
        const int kv0 = t * KVT;
        const int buf = t & 1;
        cp_wait_all();
        __syncthreads();   // tile t resident; compute on buf^1 (t-1) done

        if (t + 1 < NTILES) {   // prefetch tile t+1 into buf^1
            const int nb = buf ^ 1;
            const uint32_t* ksrc = g_Kh + wb64 + (size_t)(kv0 + KVT + kr) * 64;
            #pragma unroll
            for (int u = 0; u < 2; ++u) {
                int p  = kp + (u << 2);
                int pk = p ^ ((kr & 7) << 2);
                cp16(kh_b + (nb * 2048 + kr * 64 + pk) * 4, ksrc + p);
            }
            const uint32_t* vsrc = g_Vt16 + (size_t)(win * NTILES + t + 1) * 2048;
            #pragma unroll
            for (int u = 0; u < 2; ++u) {
                int c = tid + u * 256;
                int ch = c >> 2, grp = c & 3;
                cp16(vt_b + (nb * 2560 + ch * 20 + grp * 4) * 4, vsrc + ch * 16 + grp * 4);
            }
            cp_commit();
        }

        const uint32_t* KhS = (const uint32_t*)smem + KH_W + buf * 2048;
        const uint32_t* Vt  = (const uint32_t*)smem + VT_W + buf * 2560;

        // ---- S = Qh·Kh (single-term fp16) ----
        float S[2][4];
        #pragma unroll
        for (int nt = 0; nt < 2; ++nt)
            #pragma unroll
            for (int v = 0; v < 4; ++v) S[nt][v] = 0.0f;

        const int sA = gr << 2;
        #pragma unroll
        for (int st = 0; st < 8; ++st) {
            int pp  = (st << 3) + tig;
            int pA0 = pp ^ sA;
            int pA1 = (pp + 4) ^ sA;
            uint32_t a0 = QhS[(woff + gr) * 64 + pA0];
            uint32_t a1 = QhS[(woff + gr + 8) * 64 + pA0];
            uint32_t a2 = QhS[(woff + gr) * 64 + pA1];
            uint32_t a3 = QhS[(woff + gr + 8) * 64 + pA1];
            #pragma unroll
            for (int nt = 0; nt < 2; ++nt) {
                int kvr = kvsub + (nt << 3) + gr;       // (kvr&7)==gr
                uint32_t b0 = KhS[kvr * 64 + pA0];
                uint32_t b1 = KhS[kvr * 64 + pA1];
                mma16h(S[nt], a0, a1, a2, a3, b0, b1);
            }
        }

        // ---- mask + exp (fixed-max) + stage P (fp16x2) + local l ----
        #pragma unroll
        for (int nt = 0; nt < 2; ++nt) {
            int kvb = kv0 + kvsub + (nt << 3) + (tig << 1);
            int rk0 = regK[kvb], rk1 = regK[kvb + 1];
            float p0 = __expf(rq0 != rk0 ? S[nt][0] - 100.0f : S[nt][0]);
            float p1 = __expf(rq0 != rk1 ? S[nt][1] - 100.0f : S[nt][1]);
            float p2 = __expf(rq1 != rk0 ? S[nt][2] - 100.0f : S[nt][2]);
            float p3 = __expf(rq1 != rk1 ? S[nt][3] - 100.0f : S[nt][3]);
            l0s += p0 + p1;
            l1s += p2 + p3;
            int pc = pbase + (nt << 2) + tig;
            PbU[(woff + gr) * 20 + pc]     = hbits(__floats2half2_rn(p0, p1));
            PbU[(woff + gr + 8) * 20 + pc] = hbits(__floats2half2_rn(p2, p3));
        }
        asm volatile("bar.sync %0, 64;" :: "r"(barid) : "memory");   // pair-local

        // ---- O += P @ V (fp16 m16n8k16) on this warp's 64 channels ----
        const uint32_t* Pw = PbU + woff * 20;
        #pragma unroll
        for (int st = 0; st < 2; ++st) {
            int pb = (st << 3) + tig;
            uint32_t a0 = Pw[gr * 20 + pb];
            uint32_t a1 = Pw[(gr + 8) * 20 + pb];
            uint32_t a2 = Pw[gr * 20 + pb + 4];
            uint32_t a3 = Pw[(gr + 8) * 20 + pb + 4];
            #pragma unroll
            for (int nt = 0; nt < 8; ++nt) {
                int ch = cbase + (nt << 3) + gr;
                uint32_t v0 = Vt[ch * 20 + pb];
                uint32_t v1 = Vt[ch * 20 + pb + 4];
                mma16h(O[nt], a0, a1, a2, a3, v0, v1);
            }
        }
    }

    // ---- l reduction: quad shuffle, then cross-sub via smem ----
    l0s += __shfl_xor_sync(0xffffffffu, l0s, 1);
    l0s += __shfl_xor_sync(0xffffffffu, l0s, 2);
    l1s += __shfl_xor_sync(0xffffffffu, l1s, 1);
    l1s += __shfl_xor_sync(0xffffffffu, l1s, 2);
    __syncthreads();
    if (tig == 0) {
        SMB[(s << 6) + woff + gr]     = l0s;
        SMB[(s << 6) + woff + gr + 8] = l1s;
    }
    __syncthreads();
    float lt0 = SMB[woff + gr]     + SMB[64 + woff + gr];
    float lt1 = SMB[woff + gr + 8] + SMB[64 + woff + gr + 8];

    // ---- epilogue: normalize + scatter ----
    float inv0 = 1.0f / lt0, inv1 = 1.0f / lt1;
    int ql0 = q0 + woff + gr;
    int i0 = ql0 / 24, j0 = ql0 - 24 * i0;
    int gr0 = (sh * 24 + i0 + 12) % 96, gc0 = (sw * 24 + j0 + 12) % 96;
    int ql1 = ql0 + 8;
    int i1 = ql1 / 24, j1 = ql1 - 24 * i1;
    int gr1 = (sh * 24 + i1 + 12) % 96, gc1 = (sw * 24 + j1 + 12) % 96;
    float* d0 = outg + ((size_t)(b * 9216 + gr0 * 96 + gc0) << 7) + cbase;
    float* d1 = outg + ((size_t)(b * 9216 + gr1 * 96 + gc1) << 7) + cbase;
    #pragma unroll
    for (int nt = 0; nt < 8; ++nt) {
        int c = (nt << 3) + (tig << 1);
        *(float2*)(d0 + c) = make_float2(O[nt][0] * inv0, O[nt][1] * inv0);
        *(float2*)(d1 + c) = make_float2(O[nt][2] * inv1, O[nt][3] * inv1);
    }
}

extern "C" void kernel_launch(void* const* d_in, const int* in_sizes, int n_in,
                              void* d_out, int out_size)
{
    const float* q = (const float*)d_in[0];
    const float* k = (const float*)d_in[1];
    const float* v = (const float*)d_in[2];
    float* out = (float*)d_out;

    prep_kv2<<<NWIN * 27, 256>>>(k, v);

    cudaFuncSetAttribute(mv_attn_tc15,
                         cudaFuncAttributeMaxDynamicSharedMemorySize, SMEM_BYTES);
    dim3 grid(9, 128, 1);
    mv_attn_tc15<<<grid, NT, SMEM_BYTES>>>(q, out);
}

// round 17
// speedup vs baseline: 1.4912x; 1.0467x over previous
#include <cuda_runtime.h>
#include <cuda_fp16.h>
#include <cstdint>

// v16 = v15 with ALL fragment loads via ldmatrix (bit-identical numerics).
// B=8, M=3, H=W=96, C=128, NS=4 -> 128 windows, L=576, KV=1728.
//  prep_kv2: gather per window; K -> fp16 single plane; V -> fp16
//            TRANSPOSED [win][tile][ch][kvpair].
//  mv_attn_tc16: QK^T = Qh*Kh (fp16 m16n8k16), PV = fp16 m16n8k16.
//            Fragments loaded with ldmatrix.m8n8.x4 (A: 16 rows x 2 chunks;
//            B: 2 n-tiles x 2 k-chunks per instruction). Fixed-max softmax;
//            l reduced once at end; depth-2 cp.async double buffer.
// CTA: 256 thr (8 warps), 64 q rows; warp pair owns 16 rows; sub s=warp&1:
// S on kv half (16 rows), PV on channel half (64). KVT=32.

#define NT 256
#define KVT 32
#define NTILES 54
#define NWIN 128
#define KVLEN 1728

__device__ uint32_t g_Kh  [(size_t)NWIN * KVLEN * 64];     // fp16x2 per 2ch
__device__ uint32_t g_Vt16[(size_t)NWIN * NTILES * 2048];  // [win][tile][ch][pair]

// smem word offsets
#define QH_W    0          // u32 [64][64]              4096
#define KH_W    4096       // u32 [2][32*64]            4096
#define VT_W    8192       // u32 [2][128][20]          5120
#define PB_W    13312      // u32 [64][20]              1280
#define SMB_W   14592      // f32 [2][64]               128
#define REGK_W  14720      // char[1728]                432 words
#define SMEM_BYTES (15152 * 4)   // 60608

__device__ __forceinline__ uint32_t hbits(__half2 h) {
    return *reinterpret_cast<uint32_t*>(&h);
}
__device__ __forceinline__ void cp16(uint32_t dst, const void* src) {
    asm volatile("cp.async.cg.shared.global [%0], [%1], 16;" :: "r"(dst), "l"(src));
}
__device__ __forceinline__ void cp_commit() {
    asm volatile("cp.async.commit_group;" ::: "memory");
}
__device__ __forceinline__ void cp_wait_all() {
    asm volatile("cp.async.wait_group 0;" ::: "memory");
}
__device__ __forceinline__ void ldsm4(uint32_t& r0, uint32_t& r1,
                                      uint32_t& r2, uint32_t& r3, uint32_t a) {
    asm volatile("ldmatrix.sync.aligned.m8n8.x4.shared.b16 {%0,%1,%2,%3}, [%4];"
        : "=r"(r0), "=r"(r1), "=r"(r2), "=r"(r3) : "r"(a));
}
__device__ __forceinline__ void mma16h(float c[4],
    uint32_t a0, uint32_t a1, uint32_t a2, uint32_t a3, uint32_t b0, uint32_t b1) {
    asm volatile("mma.sync.aligned.m16n8k16.row.col.f32.f16.f16.f32 "
        "{%0,%1,%2,%3},{%4,%5,%6,%7},{%8,%9},{%0,%1,%2,%3};"
        : "+f"(c[0]), "+f"(c[1]), "+f"(c[2]), "+f"(c[3])
        : "r"(a0), "r"(a1), "r"(a2), "r"(a3), "r"(b0), "r"(b1));
}
__device__ __forceinline__ int reg1(int x) { return (x < 72) ? 0 : ((x < 84) ? 1 : 2); }

// ============ prep: gather+convert K, gather+transpose V ============
extern "C" __global__ void __launch_bounds__(256)
prep_kv2(const float* __restrict__ kg, const float* __restrict__ vg)
{
    __shared__ uint16_t sv[128 * 64];
    const int tid = threadIdx.x, blk = blockIdx.x;
    const int win = blk / 27, kb = blk - win * 27;
    const int kvbase = kb * 64;
    const int b = win >> 4, sh = (win >> 2) & 3, sw = win & 3;

    #pragma unroll
    for (int e = 0; e < 8; ++e) {
        int idx = tid + e * 256;
        int kvl = idx >> 5, c4 = (idx & 31) << 2;
        int kv = kvbase + kvl;
        int l = kv / 3, mm = kv - 3 * l;
        int i = l / 24, j = l - 24 * i;
        int grow = (sh * 24 + i + 12) % 96;
        int gcol = (sw * 24 + j + 12) % 96;
        size_t src = (((size_t)((b * 3 + mm) * 9216 + grow * 96 + gcol)) << 7) + c4;

        float4 kf = *(const float4*)(kg + src);
        __half2 h0 = __floats2half2_rn(kf.x, kf.y);
        __half2 h1 = __floats2half2_rn(kf.z, kf.w);
        size_t dst = (size_t)win * (KVLEN * 64) + (size_t)kv * 64 + (c4 >> 1);
        *(uint2*)(g_Kh + dst) = make_uint2(hbits(h0), hbits(h1));

        float4 vf = *(const float4*)(vg + src);
        float vv[4] = {vf.x, vf.y, vf.z, vf.w};
        #pragma unroll
        for (int k2 = 0; k2 < 4; ++k2) {
            int ch = c4 + k2;
            __half vh = __float2half_rn(vv[k2]);
            sv[ch * 64 + (kvl ^ ((ch & 31) << 1))] = *reinterpret_cast<uint16_t*>(&vh);
        }
    }
    __syncthreads();

    const uint32_t* svw = (const uint32_t*)sv;
    #pragma unroll
    for (int it = 0; it < 16; ++it) {
        int idx = tid + it * 256;
        int ch = idx >> 5, kp = idx & 31;
        uint32_t w = svw[ch * 32 + (kp ^ (ch & 31))];
        int tile = kb * 2 + (kp >> 4);
        int pr   = kp & 15;
        g_Vt16[(size_t)(win * NTILES + tile) * 2048 + ch * 16 + pr] = w;
    }
}

// ============ main attention kernel ============
extern "C" __global__ void __launch_bounds__(NT, 2)
mv_attn_tc16(const float* __restrict__ qg, float* __restrict__ outg)
{
    extern __shared__ float smem[];
    uint32_t* QhS = (uint32_t*)smem + QH_W;
    uint32_t* PbU = (uint32_t*)smem + PB_W;
    float*    SMB = smem + SMB_W;
    char*     regK = (char*)(smem + REGK_W);
    const uint32_t smem_u32 = (uint32_t)__cvta_generic_to_shared(smem);
    const uint32_t kh_b = smem_u32 + KH_W * 4;
    const uint32_t vt_b = smem_u32 + VT_W * 4;

    const int tid  = threadIdx.x;
    const int warp = tid >> 5;
    const int lane = tid & 31;
    const int gr   = lane >> 2;
    const int tig  = lane & 3;
    const int pair = warp >> 1;
    const int s    = warp & 1;
    const int woff = pair << 4;

    const int win = blockIdx.y;
    const int b   = win >> 4;
    const int sh  = (win >> 2) & 3;
    const int sw  = win & 3;
    const int q0  = blockIdx.x << 6;

    const float scale = 0.08838834764831845f;
    const size_t wb64 = (size_t)win * (KVLEN * 64);

    const int kr = tid >> 3;
    const int kp = (tid & 7) << 3;

    // ---- region LUT (tile() quirk: mask column = kv % 576) ----
    for (int idx = tid; idx < KVLEN; idx += NT) {
        int kcol = idx % 576;
        int i = kcol / 24, j = kcol - 24 * i;
        regK[idx] = (char)(reg1(sh * 24 + i) * 3 + reg1(sw * 24 + j));
    }

    // ---- prefetch tile 0 into buffer 0 ----
    {
        const uint32_t* ksrc = g_Kh + wb64 + (size_t)kr * 64;
        #pragma unroll
        for (int u = 0; u < 2; ++u) {
            int p  = kp + (u << 2);
            int pk = p ^ ((kr & 7) << 2);
            cp16(kh_b + (kr * 64 + pk) * 4, ksrc + p);
        }
        const uint32_t* vsrc = g_Vt16 + (size_t)(win * NTILES) * 2048;
        #pragma unroll
        for (int u = 0; u < 2; ++u) {
            int c = tid + u * 256;
            int ch = c >> 2, grp = c & 3;
            cp16(vt_b + (ch * 20 + grp * 4) * 4, vsrc + ch * 16 + grp * 4);
        }
        cp_commit();
    }

    // ---- Q: gather + scale + single-plane fp16 into smem ----
    #pragma unroll
    for (int it = 0; it < 8; ++it) {
        int idx = tid + it * NT;
        int r   = idx >> 5;
        int c4  = (idx & 31) << 2;
        int ql  = q0 + r;
        int i = ql / 24, j = ql - 24 * i;
        int grow = (sh * 24 + i + 12) % 96;
        int gcol = (sw * 24 + j + 12) % 96;
        float4 f = *(const float4*)(qg + ((size_t)(b * 9216 + grow * 96 + gcol) << 7) + c4);
        __half2 h0 = __floats2half2_rn(f.x * scale, f.y * scale);
        __half2 h1 = __floats2half2_rn(f.z * scale, f.w * scale);
        int ps = (c4 >> 1) ^ ((r & 7) << 2);
        *(uint2*)&QhS[r * 64 + ps] = make_uint2(hbits(h0), hbits(h1));
    }

    int rq0, rq1;
    {
        int ql = q0 + woff + gr;
        int i = ql / 24, j = ql - 24 * i;
        rq0 = reg1(sh * 24 + i) * 3 + reg1(sw * 24 + j);
        ql += 8; i = ql / 24; j = ql - 24 * i;
        rq1 = reg1(sh * 24 + i) * 3 + reg1(sw * 24 + j);
    }

    float O[8][4];
    #pragma unroll
    for (int nt = 0; nt < 8; ++nt)
        #pragma unroll
        for (int v = 0; v < 4; ++v) O[nt][v] = 0.0f;
    float l0s = 0.0f, l1s = 0.0f;

    const int kvsub = s << 4;      // kv half for S (16 rows)
    const int pbase = s << 3;      // pair base for P staging
    const int cbase = s << 6;      // channel half for PV
    const int barid = 1 + pair;

    // ---- ldmatrix per-lane address components ----
    const int gA   = lane >> 3;                       // 0..3 matrix group
    const int arow = woff + (lane & 15);              // A rows (Q and P)
    const int ac4  = (lane >> 4) << 2;                // A chunk offset (0/4)
    const uint32_t qa_row = smem_u32 + (QH_W + arow * 64) * 4;
    const int     sza     = (arow & 7) << 2;
    const uint32_t pp_row = smem_u32 + (PB_W + arow * 20) * 4;
    const int brow  = kvsub + ((gA >> 1) << 3) + (lane & 7);   // K rows
    const int bc4   = (gA & 1) << 2;                           // B chunk (0/4)
    const int szb   = (brow & 7) << 2;
    const int vrow7 = lane & 7;                                // V row within tile

    for (int t = 0; t < NTILES; ++t) {
        const int kv0 = t * KVT;
        const int buf = t & 1;
        cp_wait_all();
        __syncthreads();   // tile t resident; compute on buf^1 (t-1) done

        if (t + 1 < NTILES) {   // prefetch tile t+1 into buf^1
            const int nb = buf ^ 1;
            const uint32_t* ksrc = g_Kh + wb64 + (size_t)(kv0 + KVT + kr) * 64;
            #pragma unroll
            for (int u = 0; u < 2; ++u) {
                int p  = kp + (u << 2);
                int pk = p ^ ((kr & 7) << 2);
                cp16(kh_b + (nb * 2048 + kr * 64 + pk) * 4, ksrc + p);
            }
            const uint32_t* vsrc = g_Vt16 + (size_t)(win * NTILES + t + 1) * 2048;
            #pragma unroll
            for (int u = 0; u < 2; ++u) {
                int c = tid + u * 256;
                int ch = c >> 2, grp = c & 3;
                cp16(vt_b + (nb * 2560 + ch * 20 + grp * 4) * 4, vsrc + ch * 16 + grp * 4);
            }
            cp_commit();
        }

        const uint32_t kh_buf = kh_b + buf * 2048 * 4;
        const uint32_t vt_buf = vt_b + buf * 2560 * 4;

        // ---- S = Qh·Kh via ldmatrix + mma ----
        float S[2][4];
        #pragma unroll
        for (int nt = 0; nt < 2; ++nt)
            #pragma unroll
            for (int v = 0; v < 4; ++v) S[nt][v] = 0.0f;

        #pragma unroll
        for (int st = 0; st < 8; ++st) {
            uint32_t a0, a1, a2, a3, b0, b1, b2, b3;
            ldsm4(a0, a1, a2, a3, qa_row + ((((st << 3) + ac4) ^ sza) << 2));
            ldsm4(b0, b1, b2, b3,
                  kh_buf + ((brow * 64 + (((st << 3) + bc4) ^ szb)) << 2));
            mma16h(S[0], a0, a1, a2, a3, b0, b1);
            mma16h(S[1], a0, a1, a2, a3, b2, b3);
        }

        // ---- mask + exp (fixed-max) + stage P (fp16x2) + local l ----
        #pragma unroll
        for (int nt = 0; nt < 2; ++nt) {
            int kvb = kv0 + kvsub + (nt << 3) + (tig << 1);
            int rk0 = regK[kvb], rk1 = regK[kvb + 1];
            float p0 = __expf(rq0 != rk0 ? S[nt][0] - 100.0f : S[nt][0]);
            float p1 = __expf(rq0 != rk1 ? S[nt][1] - 100.0f : S[nt][1]);
            float p2 = __expf(rq1 != rk0 ? S[nt][2] - 100.0f : S[nt][2]);
            float p3 = __expf(rq1 != rk1 ? S[nt][3] - 100.0f : S[nt][3]);
            l0s += p0 + p1;
            l1s += p2 + p3;
            int pc = pbase + (nt << 2) + tig;
            PbU[(woff + gr) * 20 + pc]     = hbits(__floats2half2_rn(p0, p1));
            PbU[(woff + gr + 8) * 20 + pc] = hbits(__floats2half2_rn(p2, p3));
        }
        asm volatile("bar.sync %0, 64;" :: "r"(barid) : "memory");   // pair-local

        // ---- O += P @ V via ldmatrix + mma ----
        #pragma unroll
        for (int st = 0; st < 2; ++st) {
            uint32_t p0, p1, p2, p3;
            ldsm4(p0, p1, p2, p3, pp_row + (((st << 3) + ac4) << 2));
            #pragma unroll
            for (int np = 0; np < 4; ++np) {
                int vch = cbase + ((((np << 1) + (gA >> 1)) << 3) + vrow7);
                uint32_t v0, v1, v2, v3;
                ldsm4(v0, v1, v2, v3,
                      vt_buf + ((vch * 20 + (st << 3) + bc4) << 2));
                mma16h(O[np << 1],       p0, p1, p2, p3, v0, v1);
                mma16h(O[(np << 1) + 1], p0, p1, p2, p3, v2, v3);
            }
        }
    }

    // ---- l reduction: quad shuffle, then cross-sub via smem ----
    l0s += __shfl_xor_sync(0xffffffffu, l0s, 1);
    l0s += __shfl_xor_sync(0xffffffffu, l0s, 2);
    l1s += __shfl_xor_sync(0xffffffffu, l1s, 1);
    l1s += __shfl_xor_sync(0xffffffffu, l1s, 2);
    __syncthreads();
    if (tig == 0) {
        SMB[(s << 6) + woff + gr]     = l0s;
        SMB[(s << 6) + woff + gr + 8] = l1s;
    }
    __syncthreads();
    float lt0 = SMB[woff + gr]     + SMB[64 + woff + gr];
    float lt1 = SMB[woff + gr + 8] + SMB[64 + woff + gr + 8];

    // ---- epilogue: normalize + scatter ----
    float inv0 = 1.0f / lt0, inv1 = 1.0f / lt1;
    int ql0 = q0 + woff + gr;
    int i0 = ql0 / 24, j0 = ql0 - 24 * i0;
    int gr0 = (sh * 24 + i0 + 12) % 96, gc0 = (sw * 24 + j0 + 12) % 96;
    int ql1 = ql0 + 8;
    int i1 = ql1 / 24, j1 = ql1 - 24 * i1;
    int gr1 = (sh * 24 + i1 + 12) % 96, gc1 = (sw * 24 + j1 + 12) % 96;
    float* d0 = outg + ((size_t)(b * 9216 + gr0 * 96 + gc0) << 7) + cbase;
    float* d1 = outg + ((size_t)(b * 9216 + gr1 * 96 + gc1) << 7) + cbase;
    #pragma unroll
    for (int nt = 0; nt < 8; ++nt) {
        int c = (nt << 3) + (tig << 1);
        *(float2*)(d0 + c) = make_float2(O[nt][0] * inv0, O[nt][1] * inv0);
        *(float2*)(d1 + c) = make_float2(O[nt][2] * inv1, O[nt][3] * inv1);
    }
}

extern "C" void kernel_launch(void* const* d_in, const int* in_sizes, int n_in,
                              void* d_out, int out_size)
{
    const float* q = (const float*)d_in[0];
    const float* k = (const float*)d_in[1];
    const float* v = (const float*)d_in[2];
    float* out = (float*)d_out;

    prep_kv2<<<NWIN * 27, 256>>>(k, v);

    cudaFuncSetAttribute(mv_attn_tc16,
                         cudaFuncAttributeMaxDynamicSharedMemorySize, SMEM_BYTES);
    dim3 grid(9, 128, 1);
    mv_attn_tc16<<<grid, NT, SMEM_BYTES>>>(q, out);
}